// round 1
// baseline (speedup 1.0000x reference)
#include <cuda_runtime.h>
#include <cuda_bf16.h>

// Problem: out[b,h,o] = sum_{i,d} x[b,h,i,d] * weighted_sum[o,i] * weight[o,d]
// == GEMM: A (M=8192, K=4096) row-major  x  W2T (K=4096, N=1024)
// where W2T[k][o] = weighted_sum[o, k>>2] * weight[o, k&3].

#define M_DIM 8192
#define N_DIM 1024
#define K_DIM 4096

#define BM 128
#define BN 128
#define BK 16

// 16 MB scratch for the materialized, transposed tied weight. Static device
// global => allocation-free, graph-capture safe.
__device__ float g_w2t[(size_t)K_DIM * N_DIM];

// ---------------------------------------------------------------------------
// Kernel 1: build W2T[k][o] = ws[o, i] * weight[o, d],  k = i*4 + d
// One thread per (i, o); 4 coalesced stores each.
// ---------------------------------------------------------------------------
__global__ void build_w2t_kernel(const float* __restrict__ weight,
                                 const float* __restrict__ ws) {
    int idx = blockIdx.x * blockDim.x + threadIdx.x;   // over I*O = 1M
    int i = idx >> 10;          // 0..1023
    int o = idx & 1023;         // 0..1023
    float s = ws[o * 1024 + i];
    float w0 = weight[o * 4 + 0];
    float w1 = weight[o * 4 + 1];
    float w2 = weight[o * 4 + 2];
    float w3 = weight[o * 4 + 3];
    size_t kbase = (size_t)(i * 4) * N_DIM + o;
    g_w2t[kbase + 0 * N_DIM] = s * w0;
    g_w2t[kbase + 1 * N_DIM] = s * w1;
    g_w2t[kbase + 2 * N_DIM] = s * w2;
    g_w2t[kbase + 3 * N_DIM] = s * w3;
}

// ---------------------------------------------------------------------------
// Kernel 2: SIMT fp32 GEMM, 128x128 tile, BK=16, 256 threads, 8x8 per thread.
// ---------------------------------------------------------------------------
__global__ __launch_bounds__(256, 2)
void gemm_kernel(const float* __restrict__ A, float* __restrict__ C) {
    __shared__ float As[BK][BM];   // transposed A tile: As[k][m]
    __shared__ float Bs[BK][BN];   // Bs[k][n]

    const int tid = threadIdx.x;
    const int tx = tid & 15;       // n direction (16)
    const int ty = tid >> 4;       // m direction (16)

    const int bm = blockIdx.y * BM;
    const int bn = blockIdx.x * BN;

    const float* Aptr = A + (size_t)bm * K_DIM;
    const float* Bptr = g_w2t + bn;

    float acc[8][8];
#pragma unroll
    for (int r = 0; r < 8; r++)
#pragma unroll
        for (int c = 0; c < 8; c++) acc[r][c] = 0.0f;

    for (int k0 = 0; k0 < K_DIM; k0 += BK) {
        // --- load A tile: 128 rows x 16 cols = 512 float4; 2 per thread ---
#pragma unroll
        for (int s = 0; s < 2; s++) {
            int f = s * 256 + tid;        // 0..511
            int row = f >> 2;             // 0..127 (4 float4 per row)
            int col4 = (f & 3) * 4;       // 0,4,8,12
            float4 v = *(const float4*)(Aptr + (size_t)row * K_DIM + k0 + col4);
            As[col4 + 0][row] = v.x;
            As[col4 + 1][row] = v.y;
            As[col4 + 2][row] = v.z;
            As[col4 + 3][row] = v.w;
        }
        // --- load B tile: 16 rows x 128 cols = 512 float4; 2 per thread ---
#pragma unroll
        for (int s = 0; s < 2; s++) {
            int f = s * 256 + tid;        // 0..511
            int row = f >> 5;             // 0..15 (32 float4 per row)
            int col4 = (f & 31) * 4;      // 0..124
            float4 v = *(const float4*)(Bptr + (size_t)(k0 + row) * N_DIM + col4);
            *(float4*)&Bs[row][col4] = v;
        }
        __syncthreads();

#pragma unroll
        for (int kk = 0; kk < BK; kk++) {
            float a[8], b[8];
            float4 a0 = *(const float4*)&As[kk][ty * 4];
            float4 a1 = *(const float4*)&As[kk][ty * 4 + 64];
            float4 b0 = *(const float4*)&Bs[kk][tx * 4];
            float4 b1 = *(const float4*)&Bs[kk][tx * 4 + 64];
            a[0] = a0.x; a[1] = a0.y; a[2] = a0.z; a[3] = a0.w;
            a[4] = a1.x; a[5] = a1.y; a[6] = a1.z; a[7] = a1.w;
            b[0] = b0.x; b[1] = b0.y; b[2] = b0.z; b[3] = b0.w;
            b[4] = b1.x; b[5] = b1.y; b[6] = b1.z; b[7] = b1.w;
#pragma unroll
            for (int r = 0; r < 8; r++)
#pragma unroll
                for (int c = 0; c < 8; c++)
                    acc[r][c] = fmaf(a[r], b[c], acc[r][c]);
        }
        __syncthreads();
    }

    // --- epilogue: two float4 stores per row ---
#pragma unroll
    for (int r = 0; r < 8; r++) {
        int mrow = bm + ((r < 4) ? (ty * 4 + r) : (64 + ty * 4 + (r - 4)));
        float* crow = C + (size_t)mrow * N_DIM + bn;
        float4 o0 = make_float4(acc[r][0], acc[r][1], acc[r][2], acc[r][3]);
        float4 o1 = make_float4(acc[r][4], acc[r][5], acc[r][6], acc[r][7]);
        *(float4*)(crow + tx * 4)      = o0;
        *(float4*)(crow + tx * 4 + 64) = o1;
    }
}

// ---------------------------------------------------------------------------
extern "C" void kernel_launch(void* const* d_in, const int* in_sizes, int n_in,
                              void* d_out, int out_size) {
    const float* x      = (const float*)d_in[0];   // (4,2048,1024,4) fp32
    const float* weight = (const float*)d_in[1];   // (1024,4)
    const float* ws     = (const float*)d_in[2];   // (1024,1024)
    float* out          = (float*)d_out;           // (4,2048,1024)

    // Build transposed tied weight
    build_w2t_kernel<<<(1024 * 1024) / 256, 256>>>(weight, ws);

    // GEMM: grid (N/BN, M/BM) = (8, 64)
    dim3 grid(N_DIM / BN, M_DIM / BM);
    gemm_kernel<<<grid, 256>>>(x, out);
}

// round 3
// speedup vs baseline: 2.0952x; 2.0952x over previous
#include <cuda_runtime.h>
#include <cuda_bf16.h>
#include <cstdint>

// out[b,h,o] = sum_{i,d} x[b,h,i,d] * ws[o,i] * weight[o,d]
// => C (8192x1024) = A (8192x4096) . W2^T,  W2[n,k] = ws[n,k>>2]*weight[n,k&3]
// bf16x3 split via mma.sync (HMMA): C = Ahi*Bhi + Ahi*Blo + Alo*Bhi, fp32 accum.
// (tcgen05 is unavailable: harness lowers via compute_103 PTX, no 'a' features.)

#define M_DIM 8192
#define N_DIM 1024
#define K_DIM 4096
#define BM 128
#define BN 128
#define BK 32
#define KT (K_DIM / BK)        // 128
#define ROWB 80                // 32 bf16 (64B) + 16B pad -> conflict-free ldmatrix
#define TILE_B (128 * ROWB)    // 10240 B per tile
#define STAGE (4 * TILE_B)     // Ahi, Alo, Bhi, Blo = 40960 B
#define NSTAGE 3
#define SMEM_BYTES (NSTAGE * STAGE)

// Precomputed bf16 hi/lo planes (plain row-major).
__device__ __nv_bfloat16 g_ahi[(size_t)M_DIM * K_DIM];
__device__ __nv_bfloat16 g_alo[(size_t)M_DIM * K_DIM];
__device__ __nv_bfloat16 g_bhi[(size_t)N_DIM * K_DIM];
__device__ __nv_bfloat16 g_blo[(size_t)N_DIM * K_DIM];

// ---------------------------------------------------------------- helpers
__device__ __forceinline__ void ldsm_x4(uint32_t* r, uint32_t addr) {
    asm volatile("ldmatrix.sync.aligned.m8n8.x4.shared.b16 {%0,%1,%2,%3}, [%4];"
                 : "=r"(r[0]), "=r"(r[1]), "=r"(r[2]), "=r"(r[3]) : "r"(addr));
}
__device__ __forceinline__ void mma16816(float* c, const uint32_t* a, const uint32_t* b) {
    asm volatile(
        "mma.sync.aligned.m16n8k16.row.col.f32.bf16.bf16.f32 "
        "{%0,%1,%2,%3}, {%4,%5,%6,%7}, {%8,%9}, {%0,%1,%2,%3};"
        : "+f"(c[0]), "+f"(c[1]), "+f"(c[2]), "+f"(c[3])
        : "r"(a[0]), "r"(a[1]), "r"(a[2]), "r"(a[3]), "r"(b[0]), "r"(b[1]));
}
__device__ __forceinline__ void cp16(uint32_t dst, const void* src) {
    asm volatile("cp.async.cg.shared.global [%0], [%1], 16;"
                 :: "r"(dst), "l"(src) : "memory");
}

__device__ __forceinline__ void split2(float a, float b, uint32_t& hi, uint32_t& lo) {
    __nv_bfloat16 ha = __float2bfloat16_rn(a);
    __nv_bfloat16 hb = __float2bfloat16_rn(b);
    float la = a - __bfloat162float(ha);
    float lb = b - __bfloat162float(hb);
    hi = (uint32_t)__bfloat16_as_ushort(ha) | ((uint32_t)__bfloat16_as_ushort(hb) << 16);
    lo = (uint32_t)__bfloat16_as_ushort(__float2bfloat16_rn(la))
       | ((uint32_t)__bfloat16_as_ushort(__float2bfloat16_rn(lb)) << 16);
}

// ------------------------------------------------- convert x -> hi/lo planes
__global__ __launch_bounds__(256) void convert_x(const float* __restrict__ x) {
    size_t idx = (size_t)blockIdx.x * 256 + threadIdx.x;   // 4,194,304 threads
    size_t base = idx * 8;
    float4 t0 = *(const float4*)(x + base);
    float4 t1 = *(const float4*)(x + base + 4);
    float v[8] = {t0.x, t0.y, t0.z, t0.w, t1.x, t1.y, t1.z, t1.w};
    uint32_t hi[4], lo[4];
#pragma unroll
    for (int e = 0; e < 4; e++) split2(v[2*e], v[2*e+1], hi[e], lo[e]);
    *(uint4*)(g_ahi + base) = make_uint4(hi[0], hi[1], hi[2], hi[3]);
    *(uint4*)(g_alo + base) = make_uint4(lo[0], lo[1], lo[2], lo[3]);
}

// --------------------------------------- build W2, convert -> hi/lo planes
__global__ __launch_bounds__(256) void convert_w(const float* __restrict__ weight,
                                                 const float* __restrict__ ws) {
    size_t idx = (size_t)blockIdx.x * 256 + threadIdx.x;   // 524,288 threads
    int n  = (int)(idx >> 9);
    int kk = ((int)idx & 511) * 8;     // 8 consecutive k = 2 i-values x 4 d
    int i0 = kk >> 2;
    float2 sv = *(const float2*)(ws + (size_t)n * 1024 + i0);
    float4 wv = *(const float4*)(weight + n * 4);
    float w[4] = {wv.x, wv.y, wv.z, wv.w};
    float v[8];
#pragma unroll
    for (int d = 0; d < 4; d++) { v[d] = sv.x * w[d]; v[4+d] = sv.y * w[d]; }
    uint32_t hi[4], lo[4];
#pragma unroll
    for (int e = 0; e < 4; e++) split2(v[2*e], v[2*e+1], hi[e], lo[e]);
    size_t base = (size_t)n * K_DIM + kk;
    *(uint4*)(g_bhi + base) = make_uint4(hi[0], hi[1], hi[2], hi[3]);
    *(uint4*)(g_blo + base) = make_uint4(lo[0], lo[1], lo[2], lo[3]);
}

// ----------------------------------------------------------- HMMA GEMM
__global__ __launch_bounds__(256, 1)
void gemm_mma(float* __restrict__ out) {
    extern __shared__ uint8_t smem[];
    uint32_t sbase = (uint32_t)__cvta_generic_to_shared(smem);

    const int tid = threadIdx.x, lane = tid & 31, wid = tid >> 5;
    const int wm = wid >> 2;          // 0..1  (64 rows each)
    const int wn = wid & 3;           // 0..3  (32 cols each)
    const int nt = blockIdx.x, mt = blockIdx.y;

    float c[4][4][4];
#pragma unroll
    for (int i = 0; i < 4; i++)
#pragma unroll
        for (int j = 0; j < 4; j++)
#pragma unroll
            for (int q = 0; q < 4; q++) c[i][j][q] = 0.0f;

    const __nv_bfloat16* gsrc[4] = {
        g_ahi + (size_t)mt * BM * K_DIM,
        g_alo + (size_t)mt * BM * K_DIM,
        g_bhi + (size_t)nt * BN * K_DIM,
        g_blo + (size_t)nt * BN * K_DIM };

    auto issue = [&](int kt) {
        int k0 = kt * BK;
        uint32_t sst = sbase + (kt % NSTAGE) * STAGE;
#pragma unroll
        for (int t = 0; t < 4; t++) {
#pragma unroll
            for (int it = 0; it < 2; it++) {
                int idx = it * 256 + tid;          // 0..511
                int row = idx >> 2, ch = idx & 3;  // 128 rows x 4 chunks
                const void* src = gsrc[t] + (size_t)row * K_DIM + k0 + ch * 8;
                uint32_t dst = sst + t * TILE_B + row * ROWB + ch * 16;
                cp16(dst, src);
            }
        }
    };

    // fragment smem addressing (constant per thread)
    const int rA = wm * 64 + (lane & 15);                         // + mf*16
    const uint32_t kAofs = (((uint32_t)lane >> 4) & 1) * 8;       // + ks*16
    const int rB = wn * 32 + (lane & 7) + (((lane >> 4) & 1) * 8); // + nh*16
    const uint32_t kBofs = (((uint32_t)lane >> 3) & 1) * 8;

    // prologue: fill all 3 stages
    issue(0); asm volatile("cp.async.commit_group;" ::: "memory");
    issue(1); asm volatile("cp.async.commit_group;" ::: "memory");
    issue(2); asm volatile("cp.async.commit_group;" ::: "memory");

    for (int kt = 0; kt < KT; kt++) {
        asm volatile("cp.async.wait_group 2;" ::: "memory");
        __syncthreads();

        uint32_t sA_hi = sbase + (kt % NSTAGE) * STAGE;
        uint32_t sA_lo = sA_hi + TILE_B;
        uint32_t sB_hi = sA_hi + 2 * TILE_B;
        uint32_t sB_lo = sA_hi + 3 * TILE_B;

#pragma unroll
        for (int ks = 0; ks < 2; ks++) {
            uint32_t ka = (ks * 16 + kAofs) * 2;
            uint32_t kb = (ks * 16 + kBofs) * 2;
            uint32_t ah[4][4], al[4][4], bh[2][4], bl[2][4];
#pragma unroll
            for (int mf = 0; mf < 4; mf++)
                ldsm_x4(ah[mf], sA_hi + (uint32_t)(rA + mf * 16) * ROWB + ka);
#pragma unroll
            for (int nh = 0; nh < 2; nh++) {
                ldsm_x4(bh[nh], sB_hi + (uint32_t)(rB + nh * 16) * ROWB + kb);
                ldsm_x4(bl[nh], sB_lo + (uint32_t)(rB + nh * 16) * ROWB + kb);
            }
#pragma unroll
            for (int mf = 0; mf < 4; mf++)
                ldsm_x4(al[mf], sA_lo + (uint32_t)(rA + mf * 16) * ROWB + ka);

#pragma unroll
            for (int mf = 0; mf < 4; mf++)
#pragma unroll
                for (int nf = 0; nf < 4; nf++) {
                    const uint32_t* bfh = &bh[nf >> 1][(nf & 1) * 2];
                    const uint32_t* bfl = &bl[nf >> 1][(nf & 1) * 2];
                    mma16816(c[mf][nf], ah[mf], bfh);
                    mma16816(c[mf][nf], ah[mf], bfl);
                    mma16816(c[mf][nf], al[mf], bfh);
                }
        }
        __syncthreads();
        if (kt + NSTAGE < KT) issue(kt + NSTAGE);
        asm volatile("cp.async.commit_group;" ::: "memory");
    }

    // ---- epilogue ----
    const int gid = lane >> 2, tig = lane & 3;
#pragma unroll
    for (int mf = 0; mf < 4; mf++) {
#pragma unroll
        for (int nf = 0; nf < 4; nf++) {
            int r0 = mt * BM + wm * 64 + mf * 16 + gid;
            int col = nt * BN + wn * 32 + nf * 8 + tig * 2;
            float* p = out + (size_t)r0 * N_DIM + col;
            *(float2*)p = make_float2(c[mf][nf][0], c[mf][nf][1]);
            *(float2*)(p + 8 * N_DIM) = make_float2(c[mf][nf][2], c[mf][nf][3]);
        }
    }
}

// ---------------------------------------------------------------- launcher
extern "C" void kernel_launch(void* const* d_in, const int* in_sizes, int n_in,
                              void* d_out, int out_size) {
    const float* x      = (const float*)d_in[0];   // (4,2048,1024,4)
    const float* weight = (const float*)d_in[1];   // (1024,4)
    const float* ws     = (const float*)d_in[2];   // (1024,1024)
    float* out          = (float*)d_out;           // (4,2048,1024)

    convert_x<<<16384, 256>>>(x);
    convert_w<<<2048, 256>>>(weight, ws);

    cudaFuncSetAttribute(gemm_mma, cudaFuncAttributeMaxDynamicSharedMemorySize, SMEM_BYTES);
    dim3 grid(N_DIM / BN, M_DIM / BM);   // (8, 64), nt fastest for L2 reuse of A
    gemm_mma<<<grid, 256, SMEM_BYTES>>>(out);
}

// round 4
// speedup vs baseline: 6.2488x; 2.9824x over previous
#include <cuda_runtime.h>
#include <cuda_fp16.h>
#include <cstdint>

// out[b,h,o] = sum_{i,d} x[b,h,i,d] * ws[o,i] * weight[o,d]
// => C (8192x1024) = A (8192x4096) . W2^T,  W2[n,k] = ws[n,k>>2]*weight[n,k&3]
// Single-term fp16 HMMA GEMM (e5m10 mantissa => ~3.4e-4 L2 rel err, under 1e-3).
// Legacy mma.sync is issue-floor bound, so minimizing mma count is the win.

#define M_DIM 8192
#define N_DIM 1024
#define K_DIM 4096
#define BM 128
#define BN 128
#define BK 32
#define KT (K_DIM / BK)        // 128
#define ROWB 80                // 32 f16 (64B) + 16B pad -> conflict-free ldmatrix
#define TILE_B (128 * ROWB)    // 10240 B per tile
#define STAGE (2 * TILE_B)     // A tile + B tile = 20480 B
#define NSTAGE 4
#define SMEM_BYTES (NSTAGE * STAGE)   // 81920 B -> 2 CTAs/SM

// Precomputed fp16 operands (plain row-major).
__device__ __half g_a[(size_t)M_DIM * K_DIM];
__device__ __half g_b[(size_t)N_DIM * K_DIM];

// ---------------------------------------------------------------- helpers
__device__ __forceinline__ void ldsm_x4(uint32_t* r, uint32_t addr) {
    asm volatile("ldmatrix.sync.aligned.m8n8.x4.shared.b16 {%0,%1,%2,%3}, [%4];"
                 : "=r"(r[0]), "=r"(r[1]), "=r"(r[2]), "=r"(r[3]) : "r"(addr));
}
__device__ __forceinline__ void mma16816(float* c, const uint32_t* a, const uint32_t* b) {
    asm volatile(
        "mma.sync.aligned.m16n8k16.row.col.f32.f16.f16.f32 "
        "{%0,%1,%2,%3}, {%4,%5,%6,%7}, {%8,%9}, {%0,%1,%2,%3};"
        : "+f"(c[0]), "+f"(c[1]), "+f"(c[2]), "+f"(c[3])
        : "r"(a[0]), "r"(a[1]), "r"(a[2]), "r"(a[3]), "r"(b[0]), "r"(b[1]));
}
__device__ __forceinline__ void cp16(uint32_t dst, const void* src) {
    asm volatile("cp.async.cg.shared.global [%0], [%1], 16;"
                 :: "r"(dst), "l"(src) : "memory");
}
__device__ __forceinline__ uint32_t pack_h2(float a, float b) {
    __half2 h = __floats2half2_rn(a, b);
    return *(uint32_t*)&h;
}

// ------------------------------------------------- convert x -> fp16 plane
__global__ __launch_bounds__(256) void convert_x(const float* __restrict__ x) {
    size_t idx = (size_t)blockIdx.x * 256 + threadIdx.x;   // 4,194,304 threads
    size_t base = idx * 8;
    float4 t0 = *(const float4*)(x + base);
    float4 t1 = *(const float4*)(x + base + 4);
    uint4 o;
    o.x = pack_h2(t0.x, t0.y);
    o.y = pack_h2(t0.z, t0.w);
    o.z = pack_h2(t1.x, t1.y);
    o.w = pack_h2(t1.z, t1.w);
    *(uint4*)(g_a + base) = o;
}

// --------------------------------------- build W2 -> fp16 plane
__global__ __launch_bounds__(256) void convert_w(const float* __restrict__ weight,
                                                 const float* __restrict__ ws) {
    size_t idx = (size_t)blockIdx.x * 256 + threadIdx.x;   // 524,288 threads
    int n  = (int)(idx >> 9);
    int kk = ((int)idx & 511) * 8;     // 8 consecutive k = 2 i-values x 4 d
    int i0 = kk >> 2;
    float2 sv = *(const float2*)(ws + (size_t)n * 1024 + i0);
    float4 wv = *(const float4*)(weight + n * 4);
    uint4 o;
    o.x = pack_h2(sv.x * wv.x, sv.x * wv.y);
    o.y = pack_h2(sv.x * wv.z, sv.x * wv.w);
    o.z = pack_h2(sv.y * wv.x, sv.y * wv.y);
    o.w = pack_h2(sv.y * wv.z, sv.y * wv.w);
    *(uint4*)(g_b + (size_t)n * K_DIM + kk) = o;
}

// ----------------------------------------------------------- HMMA GEMM
__global__ __launch_bounds__(256, 2)
void gemm_mma(float* __restrict__ out) {
    extern __shared__ uint8_t smem[];
    uint32_t sbase = (uint32_t)__cvta_generic_to_shared(smem);

    const int tid = threadIdx.x, lane = tid & 31, wid = tid >> 5;
    const int wm = wid >> 2;          // 0..1  (64 rows each)
    const int wn = wid & 3;           // 0..3  (32 cols each)
    const int nt = blockIdx.x, mt = blockIdx.y;

    float c[4][4][4];
#pragma unroll
    for (int i = 0; i < 4; i++)
#pragma unroll
        for (int j = 0; j < 4; j++)
#pragma unroll
            for (int q = 0; q < 4; q++) c[i][j][q] = 0.0f;

    const __half* asrc = g_a + (size_t)mt * BM * K_DIM;
    const __half* bsrc = g_b + (size_t)nt * BN * K_DIM;

    auto issue = [&](int kt) {
        int k0 = kt * BK;
        uint32_t sst = sbase + (kt % NSTAGE) * STAGE;
        // A tile: 128 rows x 2 chunks of 16B per 256 threads -> 2 cp16/thread
#pragma unroll
        for (int it = 0; it < 2; it++) {
            int idx = it * 256 + tid;          // 0..511
            int row = idx >> 2, ch = idx & 3;  // 128 rows x 4 chunks
            cp16(sst + row * ROWB + ch * 16,
                 asrc + (size_t)row * K_DIM + k0 + ch * 8);
        }
#pragma unroll
        for (int it = 0; it < 2; it++) {
            int idx = it * 256 + tid;
            int row = idx >> 2, ch = idx & 3;
            cp16(sst + TILE_B + row * ROWB + ch * 16,
                 bsrc + (size_t)row * K_DIM + k0 + ch * 8);
        }
    };

    // fragment smem addressing (constant per thread)
    const int rA = wm * 64 + (lane & 15);                          // + mf*16
    const uint32_t kAofs = (((uint32_t)lane >> 4) & 1) * 8;        // + ks*16
    const int rB = wn * 32 + (lane & 7) + (((lane >> 4) & 1) * 8); // + nh*16
    const uint32_t kBofs = (((uint32_t)lane >> 3) & 1) * 8;

    // prologue: fill 3 of 4 stages
    issue(0); asm volatile("cp.async.commit_group;" ::: "memory");
    issue(1); asm volatile("cp.async.commit_group;" ::: "memory");
    issue(2); asm volatile("cp.async.commit_group;" ::: "memory");

    for (int kt = 0; kt < KT; kt++) {
        asm volatile("cp.async.wait_group 2;" ::: "memory");
        __syncthreads();

        uint32_t sA = sbase + (kt % NSTAGE) * STAGE;
        uint32_t sB = sA + TILE_B;

#pragma unroll
        for (int ks = 0; ks < 2; ks++) {
            uint32_t ka = (ks * 16 + kAofs) * 2;
            uint32_t kb = (ks * 16 + kBofs) * 2;
            uint32_t ah[4][4], bh[2][4];
#pragma unroll
            for (int mf = 0; mf < 4; mf++)
                ldsm_x4(ah[mf], sA + (uint32_t)(rA + mf * 16) * ROWB + ka);
#pragma unroll
            for (int nh = 0; nh < 2; nh++)
                ldsm_x4(bh[nh], sB + (uint32_t)(rB + nh * 16) * ROWB + kb);

#pragma unroll
            for (int mf = 0; mf < 4; mf++)
#pragma unroll
                for (int nf = 0; nf < 4; nf++)
                    mma16816(c[mf][nf], ah[mf], &bh[nf >> 1][(nf & 1) * 2]);
        }

        // issue into stage (kt+3)%4 == (kt-1)%4: safe after the barrier above,
        // since every warp finished reading stage kt-1 before arriving at it.
        if (kt + 3 < KT) issue(kt + 3);
        asm volatile("cp.async.commit_group;" ::: "memory");
    }

    // ---- epilogue ----
    const int gid = lane >> 2, tig = lane & 3;
#pragma unroll
    for (int mf = 0; mf < 4; mf++) {
#pragma unroll
        for (int nf = 0; nf < 4; nf++) {
            int r0 = mt * BM + wm * 64 + mf * 16 + gid;
            int col = nt * BN + wn * 32 + nf * 8 + tig * 2;
            float* p = out + (size_t)r0 * N_DIM + col;
            *(float2*)p = make_float2(c[mf][nf][0], c[mf][nf][1]);
            *(float2*)(p + 8 * N_DIM) = make_float2(c[mf][nf][2], c[mf][nf][3]);
        }
    }
}

// ---------------------------------------------------------------- launcher
extern "C" void kernel_launch(void* const* d_in, const int* in_sizes, int n_in,
                              void* d_out, int out_size) {
    const float* x      = (const float*)d_in[0];   // (4,2048,1024,4)
    const float* weight = (const float*)d_in[1];   // (1024,4)
    const float* ws     = (const float*)d_in[2];   // (1024,1024)
    float* out          = (float*)d_out;           // (4,2048,1024)

    convert_x<<<16384, 256>>>(x);
    convert_w<<<2048, 256>>>(weight, ws);

    cudaFuncSetAttribute(gemm_mma, cudaFuncAttributeMaxDynamicSharedMemorySize, SMEM_BYTES);
    dim3 grid(N_DIM / BN, M_DIM / BM);   // (8, 64), nt fastest for L2 reuse of A
    gemm_mma<<<grid, 256, SMEM_BYTES>>>(out);
}